// round 15
// baseline (speedup 1.0000x reference)
#include <cuda_runtime.h>
#include <cuda_bf16.h>
#include <cstdint>

// Problem constants
#define BATCH   16
#define NQ      1024
#define NK      1024
#define DIN     512
#define NHEADS  8
#define HDIM    64
#define BN_TOT  (BATCH * NQ)       // 16384
#define NORM_F  0.125f             // 1/sqrt(64)
#define LOG2E   1.4426950408889634f

// -------- scratch (device globals: allocation-free) --------
// g_Q holds Q pre-scaled by NORM*LOG2E and tf32-rounded; g_K/g_V tf32-rounded.
__device__ float g_Q[(size_t)NHEADS * BN_TOT * HDIM];   // [h][bn][64]
__device__ float g_K[(size_t)NHEADS * BN_TOT * HDIM];
__device__ float g_V[(size_t)NHEADS * BN_TOT * HDIM];
__device__ float g_H[(size_t)BN_TOT * DIN];             // [bn][h*64+v], tf32-rounded
__device__ unsigned long long g_Mb[(size_t)BN_TOT * (NK / 64)];  // permuted mask bits
// bf16 hi/lo split of QKV weights, layout [op][n_global(512)][k(512)]
__device__ __nv_bfloat16 g_Wbh[(size_t)3 * 512 * 512];
__device__ __nv_bfloat16 g_Wbl[(size_t)3 * 512 * 512];
// bf16 hi/lo split of inputs, layout [op][bn(16384)][k(512)]
__device__ __nv_bfloat16 g_Xbh[(size_t)3 * BN_TOT * 512];
__device__ __nv_bfloat16 g_Xbl[(size_t)3 * BN_TOT * 512];

__device__ __forceinline__ float f2tf32_rna(float x) {
    uint32_t r;
    asm("cvt.rna.tf32.f32 %0, %1;" : "=r"(r) : "f"(x));
    return __uint_as_float(r);
}

__device__ __forceinline__ float ex2_approx(float x) {
    float r;
    asm("ex2.approx.f32 %0, %1;" : "=f"(r) : "f"(x));
    return r;
}

__device__ __forceinline__ uint32_t smem_u32(const void* p) {
    uint32_t a;
    asm("{ .reg .u64 t; cvta.to.shared.u64 t, %1; cvt.u32.u64 %0, t; }"
        : "=r"(a) : "l"(p));
    return a;
}

#define CP_ASYNC16(dst_u32, src_ptr) \
    asm volatile("cp.async.cg.shared.global [%0], [%1], 16;" \
                 :: "r"(dst_u32), "l"(src_ptr) : "memory")
#define CP_COMMIT() asm volatile("cp.async.commit_group;" ::: "memory")

// m16n8k8 tf32 mma (g=lane>>2, t=lane&3):
//   A: a0(g,t) a1(g+8,t) a2(g,t+4) a3(g+8,t+4)
//   B: b0(k=t,n=g) b1(k=t+4,n=g)
//   C: c0(g,2t) c1(g,2t+1) c2(g+8,2t) c3(g+8,2t+1)
__device__ __forceinline__ void mma_tf32(float* c, const uint32_t* a, const uint32_t* b) {
    asm volatile(
        "mma.sync.aligned.m16n8k8.row.col.f32.tf32.tf32.f32 "
        "{%0,%1,%2,%3}, {%4,%5,%6,%7}, {%8,%9}, {%0,%1,%2,%3};"
        : "+f"(c[0]), "+f"(c[1]), "+f"(c[2]), "+f"(c[3])
        : "r"(a[0]), "r"(a[1]), "r"(a[2]), "r"(a[3]), "r"(b[0]), "r"(b[1]));
}

// m16n8k16 bf16 mma. Each 32-bit reg = 2 bf16 along K.
__device__ __forceinline__ void mma_bf16(float* c, const uint32_t* a,
                                         uint32_t b0, uint32_t b1) {
    asm volatile(
        "mma.sync.aligned.m16n8k16.row.col.f32.bf16.bf16.f32 "
        "{%0,%1,%2,%3}, {%4,%5,%6,%7}, {%8,%9}, {%0,%1,%2,%3};"
        : "+f"(c[0]), "+f"(c[1]), "+f"(c[2]), "+f"(c[3])
        : "r"(a[0]), "r"(a[1]), "r"(a[2]), "r"(a[3]), "r"(b0), "r"(b1));
}

// ============================================================
// W prep: split QKV weights to bf16 hi/lo, transposed to [op][n][k].
// ============================================================
__global__ __launch_bounds__(256)
void w_prep(const float* __restrict__ Wq,
            const float* __restrict__ Wk,
            const float* __restrict__ Wv)
{
    size_t idx = (size_t)blockIdx.x * 256 + threadIdx.x;   // [op][n][k]
    int k  = idx & 511;
    int n  = (idx >> 9) & 511;
    int op = (int)(idx >> 18);
    const float* W = (op == 0 ? Wq : (op == 1 ? Wk : Wv));
    float w = W[(size_t)((n >> 6) * 512 + k) * 64 + (n & 63)];
    __nv_bfloat16 hi = __float2bfloat16_rn(w);
    __nv_bfloat16 lo = __float2bfloat16_rn(w - __bfloat162float(hi));
    g_Wbh[idx] = hi;
    g_Wbl[idx] = lo;
}

// ============================================================
// X prep: split q/k/v inputs to bf16 hi/lo planes, layout [op][bn][k].
// float4 loads, uint2 stores (4 bf16).
// ============================================================
__global__ __launch_bounds__(256)
void x_prep(const float* __restrict__ q,
            const float* __restrict__ k,
            const float* __restrict__ v)
{
    size_t i4 = (size_t)blockIdx.x * 256 + threadIdx.x;    // float4 index
    size_t per_op = (size_t)BN_TOT * 512 / 4;
    int op = (int)(i4 / per_op);
    size_t off = (i4 - (size_t)op * per_op) * 4;
    const float* X = (op == 0 ? q : (op == 1 ? k : v));
    float4 xv = *(const float4*)(X + off);
    union { __nv_bfloat16 b[4]; uint2 u; } uh, ul;
    float vv[4] = {xv.x, xv.y, xv.z, xv.w};
#pragma unroll
    for (int j = 0; j < 4; ++j) {
        __nv_bfloat16 hb = __float2bfloat16_rn(vv[j]);
        uh.b[j] = hb;
        ul.b[j] = __float2bfloat16_rn(vv[j] - __bfloat162float(hb));
    }
    size_t o = (size_t)op * BN_TOT * 512 + off;
    *(uint2*)(g_Xbh + o) = uh.u;
    *(uint2*)(g_Xbl + o) = ul.u;
}

// ============================================================
// QKV projection via bf16x3 split tensor-core GEMM.
// R15: ALL staging via cp.async (pre-split X/W planes), double-buffered.
// smem (dynamic): [2] x 4 planes x 128 x QLD bf16 = 80 KB -> 2 CTAs/SM.
// grid = (128 m-tiles, 4 n-tiles, 3 ops)
// ============================================================
#define QLD 40
#define QPL (128 * QLD)            // elems per plane buffer

__global__ __launch_bounds__(256, 2)
void qkv_bf2()
{
    extern __shared__ __nv_bfloat16 smq[];
    __nv_bfloat16* sAh = smq;              // [2][QPL]
    __nv_bfloat16* sAl = smq + 2 * QPL;
    __nv_bfloat16* sWh = smq + 4 * QPL;
    __nv_bfloat16* sWl = smq + 6 * QPL;

    const int tid  = threadIdx.x;
    const int w    = tid >> 5;
    const int lane = tid & 31;
    const int g    = lane >> 2;
    const int t    = lane & 3;
    const int wm   = w & 3;
    const int wn   = w >> 2;
    const int op   = blockIdx.z;
    const int m0   = blockIdx.x * 128;
    const int n0   = blockIdx.y * 128;

    float* Cb = (op == 0 ? g_Q : (op == 1 ? g_K : g_V));
    const __nv_bfloat16* Xh = g_Xbh + ((size_t)op * BN_TOT + m0) * 512;
    const __nv_bfloat16* Xl = g_Xbl + ((size_t)op * BN_TOT + m0) * 512;
    const __nv_bfloat16* Wh = g_Wbh + ((size_t)op * 512 + n0) * 512;
    const __nv_bfloat16* Wl = g_Wbl + ((size_t)op * 512 + n0) * 512;

    // staging: per plane per chunk, 128 rows x 4 16B-chunks = 512 tasks, 2/thread
    // idx = tid + i*256 -> row = idx>>2, kg = idx&3
    const uint32_t uAh = smem_u32(sAh), uAl = smem_u32(sAl);
    const uint32_t uWh = smem_u32(sWh), uWl = smem_u32(sWl);

    float acc[2][8][4];
#pragma unroll
    for (int mi = 0; mi < 2; ++mi)
#pragma unroll
        for (int nf = 0; nf < 8; ++nf)
#pragma unroll
            for (int j = 0; j < 4; ++j) acc[mi][nf][j] = 0.f;

    // ---- prologue: issue chunk 0 into buffer 0 ----
#pragma unroll
    for (int i = 0; i < 2; ++i) {
        int idx = tid + i * 256;
        int r  = idx >> 2;
        int kg = idx & 3;
        uint32_t doff = (uint32_t)(r * QLD + kg * 8) * 2;
        size_t soff = (size_t)r * 512 + kg * 8;
        CP_ASYNC16(uAh + doff, Xh + soff);
        CP_ASYNC16(uAl + doff, Xl + soff);
        CP_ASYNC16(uWh + doff, Wh + soff);
        CP_ASYNC16(uWl + doff, Wl + soff);
    }
    CP_COMMIT();

    for (int c = 0; c < DIN / 32; ++c) {
        const int cur = c & 1;
        if (c > 0) __syncthreads();    // compute(c-1) retired -> buf cur free was issued... (buffers alternate)

        if (c < DIN / 32 - 1) {
            const int nxt = cur ^ 1;
            const int k0n = (c + 1) * 32;
#pragma unroll
            for (int i = 0; i < 2; ++i) {
                int idx = tid + i * 256;
                int r  = idx >> 2;
                int kg = idx & 3;
                uint32_t doff = (uint32_t)(nxt * QPL + r * QLD + kg * 8) * 2;
                size_t soff = (size_t)r * 512 + k0n + kg * 8;
                CP_ASYNC16(uAh + doff, Xh + soff);
                CP_ASYNC16(uAl + doff, Xl + soff);
                CP_ASYNC16(uWh + doff, Wh + soff);
                CP_ASYNC16(uWl + doff, Wl + soff);
            }
            CP_COMMIT();
            asm volatile("cp.async.wait_group 1;" ::: "memory");   // chunk c ready
        } else {
            asm volatile("cp.async.wait_group 0;" ::: "memory");
        }
        __syncthreads();

        const __nv_bfloat16* cAh = sAh + cur * QPL;
        const __nv_bfloat16* cAl = sAl + cur * QPL;
        const __nv_bfloat16* cWh = sWh + cur * QPL;
        const __nv_bfloat16* cWl = sWl + cur * QPL;

#pragma unroll
        for (int kc2 = 0; kc2 < 2; ++kc2) {
            const int kb = kc2 * 16;
            uint32_t ah[2][4], al[2][4];
#pragma unroll
            for (int mi = 0; mi < 2; ++mi) {
                int r0 = wm * 32 + mi * 16 + g;
                int r1 = r0 + 8;
                ah[mi][0] = *(const uint32_t*)(cAh + r0 * QLD + kb + 2 * t);
                ah[mi][1] = *(const uint32_t*)(cAh + r1 * QLD + kb + 2 * t);
                ah[mi][2] = *(const uint32_t*)(cAh + r0 * QLD + kb + 8 + 2 * t);
                ah[mi][3] = *(const uint32_t*)(cAh + r1 * QLD + kb + 8 + 2 * t);
                al[mi][0] = *(const uint32_t*)(cAl + r0 * QLD + kb + 2 * t);
                al[mi][1] = *(const uint32_t*)(cAl + r1 * QLD + kb + 2 * t);
                al[mi][2] = *(const uint32_t*)(cAl + r0 * QLD + kb + 8 + 2 * t);
                al[mi][3] = *(const uint32_t*)(cAl + r1 * QLD + kb + 8 + 2 * t);
            }
#pragma unroll
            for (int nf = 0; nf < 8; ++nf) {
                int col = wn * 64 + nf * 8 + g;
                uint32_t bh0 = *(const uint32_t*)(cWh + col * QLD + kb + 2 * t);
                uint32_t bh1 = *(const uint32_t*)(cWh + col * QLD + kb + 8 + 2 * t);
                uint32_t bl0 = *(const uint32_t*)(cWl + col * QLD + kb + 2 * t);
                uint32_t bl1 = *(const uint32_t*)(cWl + col * QLD + kb + 8 + 2 * t);
                mma_bf16(acc[0][nf], ah[0], bh0, bh1);   // hi*hi
                mma_bf16(acc[1][nf], ah[1], bh0, bh1);
                mma_bf16(acc[0][nf], ah[0], bl0, bl1);   // hi*lo
                mma_bf16(acc[1][nf], ah[1], bl0, bl1);
                mma_bf16(acc[0][nf], al[0], bh0, bh1);   // lo*hi
                mma_bf16(acc[1][nf], al[1], bh0, bh1);
            }
        }
    }

    // Epilogue: scatter to per-head layout, pre-rounded tf32 (Q pre-scaled).
    const float osc = (op == 0) ? (NORM_F * LOG2E) : 1.0f;
    const int hb = (n0 >> 6) + wn;
#pragma unroll
    for (int mi = 0; mi < 2; ++mi) {
        int r0 = m0 + wm * 32 + mi * 16 + g;
        float* o0 = Cb + ((size_t)hb * BN_TOT + r0) * HDIM;
        float* o1 = Cb + ((size_t)hb * BN_TOT + r0 + 8) * HDIM;
#pragma unroll
        for (int nf = 0; nf < 8; ++nf) {
            *(float2*)(o0 + nf * 8 + 2 * t) =
                make_float2(f2tf32_rna(acc[mi][nf][0] * osc), f2tf32_rna(acc[mi][nf][1] * osc));
            *(float2*)(o1 + nf * 8 + 2 * t) =
                make_float2(f2tf32_rna(acc[mi][nf][2] * osc), f2tf32_rna(acc[mi][nf][3] * osc));
        }
    }
}
#define QKV_SMEM (8 * QPL * 2)   // bytes: 2 bufs x 4 planes x 128 x QLD x 2B

// ============================================================
// Mask pack, PERMUTED layout (R13 — measured good).
// ============================================================
__global__ __launch_bounds__(256)
void pack_mask(const int* __restrict__ mask)
{
    int w = (blockIdx.x * 256 + threadIdx.x) >> 5;
    int L = threadIdx.x & 31;
    const int* src = mask + (size_t)w * 64;
    int t_lo = L >> 4;
    int nt   = (L >> 1) & 7;
    int par  = L & 1;
    int c_lo = nt * 8 + 2 * t_lo + par;
    int c_hi = nt * 8 + 2 * (t_lo + 2) + par;
    unsigned lo = __ballot_sync(0xffffffffu, src[c_lo] != 0);
    unsigned hi = __ballot_sync(0xffffffffu, src[c_hi] != 0);
    if (L == 0)
        g_Mb[w] = ((unsigned long long)hi << 32) | (unsigned long long)lo;
}

// ============================================================
// Out projection with RAW mma.sync tf32 (R13 — measured good).
// ============================================================
#define OP_LDH 40
#define OP_LDW 136

__global__ __launch_bounds__(256, 2)
void out_proj3(const float* __restrict__ A,
               const float* __restrict__ B,
               float* __restrict__ C)
{
    __shared__ float sH[128 * OP_LDH];
    __shared__ float sW[32 * OP_LDW];

    const int tid  = threadIdx.x;
    const int w    = tid >> 5;
    const int lane = tid & 31;
    const int g    = lane >> 2;
    const int t    = lane & 3;
    const int wm   = w & 3;
    const int wn   = w >> 2;
    const int m0   = blockIdx.x * 128;
    const int n0   = blockIdx.y * 128;

    const float* At = A + (size_t)m0 * DIN;
    const float* Bt = B + n0;
    const int c4b = tid & 31;

    float acc[2][8][4];
#pragma unroll
    for (int mi = 0; mi < 2; ++mi)
#pragma unroll
        for (int nf = 0; nf < 8; ++nf)
#pragma unroll
            for (int j = 0; j < 4; ++j) acc[mi][nf][j] = 0.f;

    float4 ar[4], br[4];
#pragma unroll
    for (int i = 0; i < 4; ++i) {
        int idx = tid + i * 256;
        ar[i] = *(const float4*)(At + (size_t)(idx >> 3) * DIN + (idx & 7) * 4);
        br[i] = *(const float4*)(Bt + (size_t)((tid >> 5) + i * 8) * DIN + c4b * 4);
    }
#pragma unroll
    for (int i = 0; i < 4; ++i) {
        int idx = tid + i * 256;
        *(float4*)(sH + (idx >> 3) * OP_LDH + (idx & 7) * 4) = ar[i];
        float4 bv = br[i];
        bv.x = f2tf32_rna(bv.x); bv.y = f2tf32_rna(bv.y);
        bv.z = f2tf32_rna(bv.z); bv.w = f2tf32_rna(bv.w);
        *(float4*)(sW + ((tid >> 5) + i * 8) * OP_LDW + c4b * 4) = bv;
    }
    __syncthreads();

    for (int c = 0; c < DIN / 32; ++c) {
        if (c < DIN / 32 - 1) {
            const int k0n = (c + 1) * 32;
#pragma unroll
            for (int i = 0; i < 4; ++i) {
                int idx = tid + i * 256;
                ar[i] = *(const float4*)(At + (size_t)(idx >> 3) * DIN + k0n + (idx & 7) * 4);
                br[i] = *(const float4*)(Bt + (size_t)(k0n + (tid >> 5) + i * 8) * DIN + c4b * 4);
            }
        }

#pragma unroll
        for (int kc = 0; kc < 4; ++kc) {
            uint32_t af[2][4];
#pragma unroll
            for (int mi = 0; mi < 2; ++mi) {
                const float* r0 = sH + (wm * 32 + mi * 16 + g) * OP_LDH + kc * 8;
                const float* r1 = sH + (wm * 32 + mi * 16 + g + 8) * OP_LDH + kc * 8;
                af[mi][0] = __float_as_uint(r0[t]);
                af[mi][1] = __float_as_uint(r1[t]);
                af[mi][2] = __float_as_uint(r0[t + 4]);
                af[mi][3] = __float_as_uint(r1[t + 4]);
            }
#pragma unroll
            for (int nf = 0; nf < 8; ++nf) {
                uint32_t bfr[2];
                bfr[0] = __float_as_uint(sW[(kc * 8 + t) * OP_LDW + wn * 64 + nf * 8 + g]);
                bfr[1] = __float_as_uint(sW[(kc * 8 + t + 4) * OP_LDW + wn * 64 + nf * 8 + g]);
                mma_tf32(acc[0][nf], af[0], bfr);
                mma_tf32(acc[1][nf], af[1], bfr);
            }
        }
        __syncthreads();

        if (c < DIN / 32 - 1) {
#pragma unroll
            for (int i = 0; i < 4; ++i) {
                int idx = tid + i * 256;
                *(float4*)(sH + (idx >> 3) * OP_LDH + (idx & 7) * 4) = ar[i];
                float4 bv = br[i];
                bv.x = f2tf32_rna(bv.x); bv.y = f2tf32_rna(bv.y);
                bv.z = f2tf32_rna(bv.z); bv.w = f2tf32_rna(bv.w);
                *(float4*)(sW + ((tid >> 5) + i * 8) * OP_LDW + c4b * 4) = bv;
            }
            __syncthreads();
        }
    }

#pragma unroll
    for (int mi = 0; mi < 2; ++mi) {
        float* r0 = C + (size_t)(m0 + wm * 32 + mi * 16 + g) * DIN + n0 + wn * 64;
        float* r1 = C + (size_t)(m0 + wm * 32 + mi * 16 + g + 8) * DIN + n0 + wn * 64;
#pragma unroll
        for (int nf = 0; nf < 8; ++nf) {
            *(float2*)(r0 + nf * 8 + 2 * t) = make_float2(acc[mi][nf][0], acc[mi][nf][1]);
            *(float2*)(r1 + nf * 8 + 2 * t) = make_float2(acc[mi][nf][2], acc[mi][nf][3]);
        }
    }
}

// ============================================================
// FA2-style flash attention, raw mma.sync tf32, HW EX2,
// cp.async double-buffered K/V (R14 — measured good). Unchanged.
// ============================================================
#define LDK 68
#define LDV 72
#define LDP 68
#define SKT (64 * LDK)
#define SVT (64 * LDV)
#define ATTN_SMEM ((2 * SKT + 2 * SVT + 128 * LDP) * 4)

__global__ __launch_bounds__(256, 2)
void attn_mma()
{
    extern __shared__ float sm[];
    float* sK = sm;
    float* sV = sm + 2 * SKT;
    float* sP = sm + 2 * SKT + 2 * SVT;

    const int tid  = threadIdx.x;
    const int w    = tid >> 5;
    const int lane = tid & 31;
    const int g    = lane >> 2;
    const int t    = lane & 3;
    const int q0   = blockIdx.x * 128;
    const int b    = blockIdx.y;
    const int h    = blockIdx.z;

    const float* Qg = g_Q + ((size_t)(h * BATCH + b) * NQ + q0) * HDIM;
    const float* Kg = g_K + (size_t)(h * BATCH + b) * NK * HDIM;
    const float* Vg = g_V + (size_t)(h * BATCH + b) * NK * HDIM;

    const int sr  = tid >> 4;
    const int sc4 = (tid & 15) * 4;
    const uint32_t sKu = smem_u32(sK);
    const uint32_t sVu = smem_u32(sV);

    uint32_t qf[8][4];
#pragma unroll
    for (int kc = 0; kc < 8; ++kc) {
        const uint32_t* r0 = (const uint32_t*)(Qg + (size_t)(w * 16 + g) * HDIM + kc * 8);
        const uint32_t* r1 = (const uint32_t*)(Qg + (size_t)(w * 16 + g + 8) * HDIM + kc * 8);
        qf[kc][0] = r0[t];
        qf[kc][1] = r1[t];
        qf[kc][2] = r0[t + 4];
        qf[kc][3] = r1[t + 4];
    }

    float oacc[8][4];
#pragma unroll
    for (int nt = 0; nt < 8; ++nt)
#pragma unroll
        for (int j = 0; j < 4; ++j) oacc[nt][j] = 0.f;
    float m0 = -1e30f, m1 = -1e30f;
    float l0 = 0.f, l1 = 0.f;

    const unsigned long long* mb_row0 = g_Mb + ((size_t)b * NQ + q0 + w * 16 + g) * (NK / 64);
    const unsigned long long* mb_row1 = mb_row0 + 8 * (NK / 64);
    float* sPw = sP + (w * 16) * LDP;
    const int tsh = t * 16;

#pragma unroll
    for (int i = 0; i < 4; ++i) {
        int r = sr + i * 16;
        CP_ASYNC16(sKu + (r * LDK + sc4) * 4, Kg + (size_t)r * HDIM + sc4);
        CP_ASYNC16(sVu + (r * LDV + sc4) * 4, Vg + (size_t)r * HDIM + sc4);
    }
    CP_COMMIT();

    for (int kt = 0; kt < NK / 64; ++kt) {
        const int cur = kt & 1;
        __syncthreads();

        if (kt < NK / 64 - 1) {
            const int nxt = cur ^ 1;
            const float* Kn = Kg + (size_t)(kt + 1) * 64 * HDIM;
            const float* Vn = Vg + (size_t)(kt + 1) * 64 * HDIM;
#pragma unroll
            for (int i = 0; i < 4; ++i) {
                int r = sr + i * 16;
                CP_ASYNC16(sKu + (nxt * SKT + r * LDK + sc4) * 4, Kn + (size_t)r * HDIM + sc4);
                CP_ASYNC16(sVu + (nxt * SVT + r * LDV + sc4) * 4, Vn + (size_t)r * HDIM + sc4);
            }
            CP_COMMIT();
            asm volatile("cp.async.wait_group 1;" ::: "memory");
        } else {
            asm volatile("cp.async.wait_group 0;" ::: "memory");
        }
        __syncthreads();

        const float* sKc = sK + cur * SKT;
        const float* sVc = sV + cur * SVT;

        float sacc[8][4];
#pragma unroll
        for (int nt = 0; nt < 8; ++nt) {
#pragma unroll
            for (int j = 0; j < 4; ++j) sacc[nt][j] = 0.f;
#pragma unroll
            for (int kc = 0; kc < 8; ++kc) {
                uint32_t bfr[2];
                const float* kb = sKc + (nt * 8 + g) * LDK + kc * 8;
                bfr[0] = __float_as_uint(kb[t]);
                bfr[1] = __float_as_uint(kb[t + 4]);
                mma_tf32(sacc[nt], qf[kc], bfr);
            }
        }

        uint32_t ch0 = (uint32_t)(mb_row0[kt] >> tsh) & 0xffffu;
        uint32_t ch1 = (uint32_t)(mb_row1[kt] >> tsh) & 0xffffu;
        float tmax0 = -1e30f, tmax1 = -1e30f;
#pragma unroll
        for (int nt = 0; nt < 8; ++nt) {
            if (ch0 & (1u << (2 * nt)))     sacc[nt][0] = -1e30f;
            if (ch0 & (2u << (2 * nt)))     sacc[nt][1] = -1e30f;
            if (ch1 & (1u << (2 * nt)))     sacc[nt][2] = -1e30f;
            if (ch1 & (2u << (2 * nt)))     sacc[nt][3] = -1e30f;
            tmax0 = fmaxf(tmax0, fmaxf(sacc[nt][0], sacc[nt][1]));
            tmax1 = fmaxf(tmax1, fmaxf(sacc[nt][2], sacc[nt][3]));
        }
        tmax0 = fmaxf(tmax0, __shfl_xor_sync(0xffffffffu, tmax0, 1));
        tmax0 = fmaxf(tmax0, __shfl_xor_sync(0xffffffffu, tmax0, 2));
        tmax1 = fmaxf(tmax1, __shfl_xor_sync(0xffffffffu, tmax1, 1));
        tmax1 = fmaxf(tmax1, __shfl_xor_sync(0xffffffffu, tmax1, 2));

        float mn0 = fmaxf(m0, tmax0);
        float mn1 = fmaxf(m1, tmax1);
        float sc0 = ex2_approx(m0 - mn0);
        float sc1 = ex2_approx(m1 - mn1);
        m0 = mn0; m1 = mn1;

        float ps0 = 0.f, ps1 = 0.f;
#pragma unroll
        for (int nt = 0; nt < 8; ++nt) {
            float p0 = ex2_approx(sacc[nt][0] - mn0);
            float p1 = ex2_approx(sacc[nt][1] - mn0);
            float p2 = ex2_approx(sacc[nt][2] - mn1);
            float p3 = ex2_approx(sacc[nt][3] - mn1);
            ps0 += p0 + p1;
            ps1 += p2 + p3;
            float2 lo = make_float2(f2tf32_rna(p0), f2tf32_rna(p1));
            float2 hi = make_float2(f2tf32_rna(p2), f2tf32_rna(p3));
            *(float2*)(sPw + g * LDP + nt * 8 + 2 * t) = lo;
            *(float2*)(sPw + (g + 8) * LDP + nt * 8 + 2 * t) = hi;
        }
        ps0 += __shfl_xor_sync(0xffffffffu, ps0, 1);
        ps0 += __shfl_xor_sync(0xffffffffu, ps0, 2);
        ps1 += __shfl_xor_sync(0xffffffffu, ps1, 1);
        ps1 += __shfl_xor_sync(0xffffffffu, ps1, 2);
        l0 = l0 * sc0 + ps0;
        l1 = l1 * sc1 + ps1;

#pragma unroll
        for (int nt = 0; nt < 8; ++nt) {
            oacc[nt][0] *= sc0; oacc[nt][1] *= sc0;
            oacc[nt][2] *= sc1; oacc[nt][3] *= sc1;
        }
        __syncwarp();

#pragma unroll
        for (int kc = 0; kc < 8; ++kc) {
            uint32_t pa[4];
            const float* p0r = sPw + g * LDP + kc * 8;
            const float* p1r = sPw + (g + 8) * LDP + kc * 8;
            pa[0] = __float_as_uint(p0r[t]);
            pa[1] = __float_as_uint(p1r[t]);
            pa[2] = __float_as_uint(p0r[t + 4]);
            pa[3] = __float_as_uint(p1r[t + 4]);
#pragma unroll
            for (int nt = 0; nt < 8; ++nt) {
                uint32_t bfr[2];
                bfr[0] = __float_as_uint(sVc[(kc * 8 + t) * LDV + nt * 8 + g]);
                bfr[1] = __float_as_uint(sVc[(kc * 8 + t + 4) * LDV + nt * 8 + g]);
                mma_tf32(oacc[nt], pa, bfr);
            }
        }
        __syncwarp();
    }

    float inv0 = (l0 > 0.f) ? (1.f / l0) : 0.f;
    float inv1 = (l1 > 0.f) ? (1.f / l1) : 0.f;
    float* o0 = g_H + ((size_t)(b * NQ + q0 + w * 16 + g)) * DIN + h * HDIM;
    float* o1 = g_H + ((size_t)(b * NQ + q0 + w * 16 + g + 8)) * DIN + h * HDIM;
#pragma unroll
    for (int nt = 0; nt < 8; ++nt) {
        *(float2*)(o0 + nt * 8 + 2 * t) =
            make_float2(f2tf32_rna(oacc[nt][0] * inv0), f2tf32_rna(oacc[nt][1] * inv0));
        *(float2*)(o1 + nt * 8 + 2 * t) =
            make_float2(f2tf32_rna(oacc[nt][2] * inv1), f2tf32_rna(oacc[nt][3] * inv1));
    }
}

// ============================================================
extern "C" void kernel_launch(void* const* d_in, const int* in_sizes, int n_in,
                              void* d_out, int out_size)
{
    const float* q  = (const float*)d_in[0];
    const float* k  = (const float*)d_in[1];
    const float* v  = (const float*)d_in[2];
    const int*   mask = (const int*)d_in[3];
    const float* Wq = (const float*)d_in[4];
    const float* Wk = (const float*)d_in[5];
    const float* Wv = (const float*)d_in[6];
    const float* Wo = (const float*)d_in[7];
    float* out = (float*)d_out;

    float *pH;
    cudaGetSymbolAddress((void**)&pH, g_H);

    static bool attr_set = false;
    if (!attr_set) {
        cudaFuncSetAttribute(attn_mma,
                             cudaFuncAttributeMaxDynamicSharedMemorySize,
                             ATTN_SMEM);
        cudaFuncSetAttribute(qkv_bf2,
                             cudaFuncAttributeMaxDynamicSharedMemorySize,
                             QKV_SMEM);
        attr_set = true;
    }

    // Split weights and inputs to bf16 hi/lo planes
    w_prep<<<(3 * 512 * 512) / 256, 256>>>(Wq, Wk, Wv);
    x_prep<<<(3 * BN_TOT * 512 / 4) / 256, 256>>>(q, k, v);

    // QKV projections: bf16x3 tensor-core GEMM, fully cp.async pipelined
    qkv_bf2<<<dim3(BN_TOT / 128, DIN / 128, 3), 256, QKV_SMEM>>>();

    // Pack mask to permuted bitmasks
    pack_mask<<<(BN_TOT * (NK / 64)) / 8, 256>>>(mask);

    // Flash attention (raw mma.sync tf32, cp.async double-buffered K/V)
    attn_mma<<<dim3(NQ / 128, BATCH, NHEADS), 256, ATTN_SMEM>>>();

    // Output projection: raw mma.sync tf32
    out_proj3<<<dim3(BN_TOT / 128, DIN / 128), 256>>>(pH, Wo, out);
}

// round 16
// speedup vs baseline: 1.5177x; 1.5177x over previous
#include <cuda_runtime.h>
#include <cuda_bf16.h>
#include <cstdint>

// Problem constants
#define BATCH   16
#define NQ      1024
#define NK      1024
#define DIN     512
#define NHEADS  8
#define HDIM    64
#define BN_TOT  (BATCH * NQ)       // 16384
#define NORM_F  0.125f             // 1/sqrt(64)
#define LOG2E   1.4426950408889634f

// -------- scratch (device globals: allocation-free) --------
// g_Q holds Q pre-scaled by NORM*LOG2E and tf32-rounded; g_K/g_V tf32-rounded.
__device__ float g_Q[(size_t)NHEADS * BN_TOT * HDIM];   // [h][bn][64]
__device__ float g_K[(size_t)NHEADS * BN_TOT * HDIM];
__device__ float g_V[(size_t)NHEADS * BN_TOT * HDIM];
__device__ float g_H[(size_t)BN_TOT * DIN];             // [bn][h*64+v], tf32-rounded
__device__ unsigned long long g_Mb[(size_t)BN_TOT * (NK / 64)];  // permuted mask bits
// bf16 hi/lo split of QKV weights, layout [op][n_global(512)][k(512)]
__device__ __nv_bfloat16 g_Wbh[(size_t)3 * 512 * 512];
__device__ __nv_bfloat16 g_Wbl[(size_t)3 * 512 * 512];

__device__ __forceinline__ float f2tf32_rna(float x) {
    uint32_t r;
    asm("cvt.rna.tf32.f32 %0, %1;" : "=r"(r) : "f"(x));
    return __uint_as_float(r);
}

__device__ __forceinline__ float ex2_approx(float x) {
    float r;
    asm("ex2.approx.f32 %0, %1;" : "=f"(r) : "f"(x));
    return r;
}

__device__ __forceinline__ uint32_t smem_u32(const void* p) {
    uint32_t a;
    asm("{ .reg .u64 t; cvta.to.shared.u64 t, %1; cvt.u32.u64 %0, t; }"
        : "=r"(a) : "l"(p));
    return a;
}

#define CP_ASYNC16(dst_u32, src_ptr) \
    asm volatile("cp.async.cg.shared.global [%0], [%1], 16;" \
                 :: "r"(dst_u32), "l"(src_ptr) : "memory")
#define CP_COMMIT() asm volatile("cp.async.commit_group;" ::: "memory")

// m16n8k8 tf32 mma (g=lane>>2, t=lane&3):
//   A: a0(g,t) a1(g+8,t) a2(g,t+4) a3(g+8,t+4)
//   B: b0(k=t,n=g) b1(k=t+4,n=g)
//   C: c0(g,2t) c1(g,2t+1) c2(g+8,2t) c3(g+8,2t+1)
__device__ __forceinline__ void mma_tf32(float* c, const uint32_t* a, const uint32_t* b) {
    asm volatile(
        "mma.sync.aligned.m16n8k8.row.col.f32.tf32.tf32.f32 "
        "{%0,%1,%2,%3}, {%4,%5,%6,%7}, {%8,%9}, {%0,%1,%2,%3};"
        : "+f"(c[0]), "+f"(c[1]), "+f"(c[2]), "+f"(c[3])
        : "r"(a[0]), "r"(a[1]), "r"(a[2]), "r"(a[3]), "r"(b[0]), "r"(b[1]));
}

// m16n8k16 bf16 mma. Each 32-bit reg = 2 bf16 along K.
__device__ __forceinline__ void mma_bf16(float* c, const uint32_t* a,
                                         uint32_t b0, uint32_t b1) {
    asm volatile(
        "mma.sync.aligned.m16n8k16.row.col.f32.bf16.bf16.f32 "
        "{%0,%1,%2,%3}, {%4,%5,%6,%7}, {%8,%9}, {%0,%1,%2,%3};"
        : "+f"(c[0]), "+f"(c[1]), "+f"(c[2]), "+f"(c[3])
        : "r"(a[0]), "r"(a[1]), "r"(a[2]), "r"(a[3]), "r"(b0), "r"(b1));
}

// ============================================================
// W prep: split QKV weights to bf16 hi/lo, transposed to [op][n][k].
// ============================================================
__global__ __launch_bounds__(256)
void w_prep(const float* __restrict__ Wq,
            const float* __restrict__ Wk,
            const float* __restrict__ Wv)
{
    size_t idx = (size_t)blockIdx.x * 256 + threadIdx.x;   // [op][n][k]
    int k  = idx & 511;
    int n  = (idx >> 9) & 511;
    int op = (int)(idx >> 18);
    const float* W = (op == 0 ? Wq : (op == 1 ? Wk : Wv));
    float w = W[(size_t)((n >> 6) * 512 + k) * 64 + (n & 63)];
    __nv_bfloat16 hi = __float2bfloat16_rn(w);
    __nv_bfloat16 lo = __float2bfloat16_rn(w - __bfloat162float(hi));
    g_Wbh[idx] = hi;
    g_Wbl[idx] = lo;
}

// ============================================================
// QKV projection via bf16x3 split tensor-core GEMM (R13 — measured best).
// Inline LDG+split staging; epilogue pre-rounds to tf32 (Q pre-scaled).
// grid = (128 m-tiles, 4 n-tiles, 3 ops)
// ============================================================
#define QLD 40

__global__ __launch_bounds__(256, 2)
void qkv_bf(const float* __restrict__ q,
            const float* __restrict__ k,
            const float* __restrict__ v)
{
    __shared__ __nv_bfloat16 sAh[128 * QLD];
    __shared__ __nv_bfloat16 sAl[128 * QLD];
    __shared__ __nv_bfloat16 sWh[128 * QLD];
    __shared__ __nv_bfloat16 sWl[128 * QLD];

    const int tid  = threadIdx.x;
    const int w    = tid >> 5;
    const int lane = tid & 31;
    const int g    = lane >> 2;
    const int t    = lane & 3;
    const int wm   = w & 3;
    const int wn   = w >> 2;
    const int op   = blockIdx.z;
    const int m0   = blockIdx.x * 128;
    const int n0   = blockIdx.y * 128;

    const float* X = (op == 0 ? q : (op == 1 ? k : v));
    float* Cb      = (op == 0 ? g_Q : (op == 1 ? g_K : g_V));
    const __nv_bfloat16* Wh = g_Wbh + ((size_t)op * 512 + n0) * 512;
    const __nv_bfloat16* Wl = g_Wbl + ((size_t)op * 512 + n0) * 512;

    float acc[2][8][4];
#pragma unroll
    for (int mi = 0; mi < 2; ++mi)
#pragma unroll
        for (int nf = 0; nf < 8; ++nf)
#pragma unroll
            for (int j = 0; j < 4; ++j) acc[mi][nf][j] = 0.f;

    for (int c = 0; c < DIN / 32; ++c) {
        const int k0 = c * 32;
        if (c > 0) __syncthreads();

#pragma unroll
        for (int i = 0; i < 4; ++i) {
            int idx = tid + i * 256;
            int m  = idx >> 3;
            int kg = idx & 7;
            float4 xv = *(const float4*)(X + (size_t)(m0 + m) * DIN + k0 + kg * 4);
            union { __nv_bfloat16 b[4]; uint2 u; } uh, ul;
            float vv[4] = {xv.x, xv.y, xv.z, xv.w};
#pragma unroll
            for (int j = 0; j < 4; ++j) {
                __nv_bfloat16 hb = __float2bfloat16_rn(vv[j]);
                uh.b[j] = hb;
                ul.b[j] = __float2bfloat16_rn(vv[j] - __bfloat162float(hb));
            }
            *(uint2*)(sAh + m * QLD + kg * 4) = uh.u;
            *(uint2*)(sAl + m * QLD + kg * 4) = ul.u;
        }
#pragma unroll
        for (int i = 0; i < 2; ++i) {
            int s  = tid + i * 256;
            int n  = s >> 2;
            int kg = s & 3;
            *(uint4*)(sWh + n * QLD + kg * 8) =
                *(const uint4*)(Wh + (size_t)n * 512 + k0 + kg * 8);
            *(uint4*)(sWl + n * QLD + kg * 8) =
                *(const uint4*)(Wl + (size_t)n * 512 + k0 + kg * 8);
        }
        __syncthreads();

#pragma unroll
        for (int kc2 = 0; kc2 < 2; ++kc2) {
            const int kb = kc2 * 16;
            uint32_t ah[2][4], al[2][4];
#pragma unroll
            for (int mi = 0; mi < 2; ++mi) {
                int r0 = wm * 32 + mi * 16 + g;
                int r1 = r0 + 8;
                ah[mi][0] = *(const uint32_t*)(sAh + r0 * QLD + kb + 2 * t);
                ah[mi][1] = *(const uint32_t*)(sAh + r1 * QLD + kb + 2 * t);
                ah[mi][2] = *(const uint32_t*)(sAh + r0 * QLD + kb + 8 + 2 * t);
                ah[mi][3] = *(const uint32_t*)(sAh + r1 * QLD + kb + 8 + 2 * t);
                al[mi][0] = *(const uint32_t*)(sAl + r0 * QLD + kb + 2 * t);
                al[mi][1] = *(const uint32_t*)(sAl + r1 * QLD + kb + 2 * t);
                al[mi][2] = *(const uint32_t*)(sAl + r0 * QLD + kb + 8 + 2 * t);
                al[mi][3] = *(const uint32_t*)(sAl + r1 * QLD + kb + 8 + 2 * t);
            }
#pragma unroll
            for (int nf = 0; nf < 8; ++nf) {
                int col = wn * 64 + nf * 8 + g;
                uint32_t bh0 = *(const uint32_t*)(sWh + col * QLD + kb + 2 * t);
                uint32_t bh1 = *(const uint32_t*)(sWh + col * QLD + kb + 8 + 2 * t);
                uint32_t bl0 = *(const uint32_t*)(sWl + col * QLD + kb + 2 * t);
                uint32_t bl1 = *(const uint32_t*)(sWl + col * QLD + kb + 8 + 2 * t);
                mma_bf16(acc[0][nf], ah[0], bh0, bh1);   // hi*hi
                mma_bf16(acc[1][nf], ah[1], bh0, bh1);
                mma_bf16(acc[0][nf], ah[0], bl0, bl1);   // hi*lo
                mma_bf16(acc[1][nf], ah[1], bl0, bl1);
                mma_bf16(acc[0][nf], al[0], bh0, bh1);   // lo*hi
                mma_bf16(acc[1][nf], al[1], bh0, bh1);
            }
        }
    }

    const float osc = (op == 0) ? (NORM_F * LOG2E) : 1.0f;
    const int hb = (n0 >> 6) + wn;
#pragma unroll
    for (int mi = 0; mi < 2; ++mi) {
        int r0 = m0 + wm * 32 + mi * 16 + g;
        float* o0 = Cb + ((size_t)hb * BN_TOT + r0) * HDIM;
        float* o1 = Cb + ((size_t)hb * BN_TOT + r0 + 8) * HDIM;
#pragma unroll
        for (int nf = 0; nf < 8; ++nf) {
            *(float2*)(o0 + nf * 8 + 2 * t) =
                make_float2(f2tf32_rna(acc[mi][nf][0] * osc), f2tf32_rna(acc[mi][nf][1] * osc));
            *(float2*)(o1 + nf * 8 + 2 * t) =
                make_float2(f2tf32_rna(acc[mi][nf][2] * osc), f2tf32_rna(acc[mi][nf][3] * osc));
        }
    }
}

// ============================================================
// Mask pack, R16: coalesced int2 loads + REDUX assembly.
// Lane L holds elements e0=2L, e1=2L+1 of the 64-int word.
// Permuted position pos(e) = ((e>>1)&3)*16 + (e>>3)*2 + (e&1);
// pos(e0) = (L&3)*16 + (L>>2)*2, pos(e1) = pos(e0)+1 (same formula as R13
// ballot version -> bit-identical output).
// ============================================================
__global__ __launch_bounds__(256)
void pack_mask(const int* __restrict__ mask)
{
    int w = (blockIdx.x * 256 + threadIdx.x) >> 5;   // word index
    int L = threadIdx.x & 31;
    int2 m2 = *(const int2*)(mask + (size_t)w * 64 + 2 * L);
    int pos0 = (L & 3) * 16 + (L >> 2) * 2;
    unsigned long long bits =
        ((unsigned long long)((m2.x != 0 ? 1u : 0u) | (m2.y != 0 ? 2u : 0u))) << pos0;
    unsigned lo = __reduce_or_sync(0xffffffffu, (unsigned)bits);
    unsigned hi = __reduce_or_sync(0xffffffffu, (unsigned)(bits >> 32));
    if (L == 0)
        g_Mb[w] = ((unsigned long long)hi << 32) | (unsigned long long)lo;
}

// ============================================================
// Out projection with RAW mma.sync tf32 (R13 — measured good).
// ============================================================
#define OP_LDH 40
#define OP_LDW 136

__global__ __launch_bounds__(256, 2)
void out_proj3(const float* __restrict__ A,
               const float* __restrict__ B,
               float* __restrict__ C)
{
    __shared__ float sH[128 * OP_LDH];
    __shared__ float sW[32 * OP_LDW];

    const int tid  = threadIdx.x;
    const int w    = tid >> 5;
    const int lane = tid & 31;
    const int g    = lane >> 2;
    const int t    = lane & 3;
    const int wm   = w & 3;
    const int wn   = w >> 2;
    const int m0   = blockIdx.x * 128;
    const int n0   = blockIdx.y * 128;

    const float* At = A + (size_t)m0 * DIN;
    const float* Bt = B + n0;
    const int c4b = tid & 31;

    float acc[2][8][4];
#pragma unroll
    for (int mi = 0; mi < 2; ++mi)
#pragma unroll
        for (int nf = 0; nf < 8; ++nf)
#pragma unroll
            for (int j = 0; j < 4; ++j) acc[mi][nf][j] = 0.f;

    float4 ar[4], br[4];
#pragma unroll
    for (int i = 0; i < 4; ++i) {
        int idx = tid + i * 256;
        ar[i] = *(const float4*)(At + (size_t)(idx >> 3) * DIN + (idx & 7) * 4);
        br[i] = *(const float4*)(Bt + (size_t)((tid >> 5) + i * 8) * DIN + c4b * 4);
    }
#pragma unroll
    for (int i = 0; i < 4; ++i) {
        int idx = tid + i * 256;
        *(float4*)(sH + (idx >> 3) * OP_LDH + (idx & 7) * 4) = ar[i];
        float4 bv = br[i];
        bv.x = f2tf32_rna(bv.x); bv.y = f2tf32_rna(bv.y);
        bv.z = f2tf32_rna(bv.z); bv.w = f2tf32_rna(bv.w);
        *(float4*)(sW + ((tid >> 5) + i * 8) * OP_LDW + c4b * 4) = bv;
    }
    __syncthreads();

    for (int c = 0; c < DIN / 32; ++c) {
        if (c < DIN / 32 - 1) {
            const int k0n = (c + 1) * 32;
#pragma unroll
            for (int i = 0; i < 4; ++i) {
                int idx = tid + i * 256;
                ar[i] = *(const float4*)(At + (size_t)(idx >> 3) * DIN + k0n + (idx & 7) * 4);
                br[i] = *(const float4*)(Bt + (size_t)(k0n + (tid >> 5) + i * 8) * DIN + c4b * 4);
            }
        }

#pragma unroll
        for (int kc = 0; kc < 4; ++kc) {
            uint32_t af[2][4];
#pragma unroll
            for (int mi = 0; mi < 2; ++mi) {
                const float* r0 = sH + (wm * 32 + mi * 16 + g) * OP_LDH + kc * 8;
                const float* r1 = sH + (wm * 32 + mi * 16 + g + 8) * OP_LDH + kc * 8;
                af[mi][0] = __float_as_uint(r0[t]);
                af[mi][1] = __float_as_uint(r1[t]);
                af[mi][2] = __float_as_uint(r0[t + 4]);
                af[mi][3] = __float_as_uint(r1[t + 4]);
            }
#pragma unroll
            for (int nf = 0; nf < 8; ++nf) {
                uint32_t bfr[2];
                bfr[0] = __float_as_uint(sW[(kc * 8 + t) * OP_LDW + wn * 64 + nf * 8 + g]);
                bfr[1] = __float_as_uint(sW[(kc * 8 + t + 4) * OP_LDW + wn * 64 + nf * 8 + g]);
                mma_tf32(acc[0][nf], af[0], bfr);
                mma_tf32(acc[1][nf], af[1], bfr);
            }
        }
        __syncthreads();

        if (c < DIN / 32 - 1) {
#pragma unroll
            for (int i = 0; i < 4; ++i) {
                int idx = tid + i * 256;
                *(float4*)(sH + (idx >> 3) * OP_LDH + (idx & 7) * 4) = ar[i];
                float4 bv = br[i];
                bv.x = f2tf32_rna(bv.x); bv.y = f2tf32_rna(bv.y);
                bv.z = f2tf32_rna(bv.z); bv.w = f2tf32_rna(bv.w);
                *(float4*)(sW + ((tid >> 5) + i * 8) * OP_LDW + c4b * 4) = bv;
            }
            __syncthreads();
        }
    }

#pragma unroll
    for (int mi = 0; mi < 2; ++mi) {
        float* r0 = C + (size_t)(m0 + wm * 32 + mi * 16 + g) * DIN + n0 + wn * 64;
        float* r1 = C + (size_t)(m0 + wm * 32 + mi * 16 + g + 8) * DIN + n0 + wn * 64;
#pragma unroll
        for (int nf = 0; nf < 8; ++nf) {
            *(float2*)(r0 + nf * 8 + 2 * t) = make_float2(acc[mi][nf][0], acc[mi][nf][1]);
            *(float2*)(r1 + nf * 8 + 2 * t) = make_float2(acc[mi][nf][2], acc[mi][nf][3]);
        }
    }
}

// ============================================================
// FA2-style flash attention, raw mma.sync tf32, HW EX2,
// cp.async double-buffered K/V (R14 — measured best). Unchanged.
// ============================================================
#define LDK 68
#define LDV 72
#define LDP 68
#define SKT (64 * LDK)
#define SVT (64 * LDV)
#define ATTN_SMEM ((2 * SKT + 2 * SVT + 128 * LDP) * 4)

__global__ __launch_bounds__(256, 2)
void attn_mma()
{
    extern __shared__ float sm[];
    float* sK = sm;
    float* sV = sm + 2 * SKT;
    float* sP = sm + 2 * SKT + 2 * SVT;

    const int tid  = threadIdx.x;
    const int w    = tid >> 5;
    const int lane = tid & 31;
    const int g    = lane >> 2;
    const int t    = lane & 3;
    const int q0   = blockIdx.x * 128;
    const int b    = blockIdx.y;
    const int h    = blockIdx.z;

    const float* Qg = g_Q + ((size_t)(h * BATCH + b) * NQ + q0) * HDIM;
    const float* Kg = g_K + (size_t)(h * BATCH + b) * NK * HDIM;
    const float* Vg = g_V + (size_t)(h * BATCH + b) * NK * HDIM;

    const int sr  = tid >> 4;
    const int sc4 = (tid & 15) * 4;
    const uint32_t sKu = smem_u32(sK);
    const uint32_t sVu = smem_u32(sV);

    uint32_t qf[8][4];
#pragma unroll
    for (int kc = 0; kc < 8; ++kc) {
        const uint32_t* r0 = (const uint32_t*)(Qg + (size_t)(w * 16 + g) * HDIM + kc * 8);
        const uint32_t* r1 = (const uint32_t*)(Qg + (size_t)(w * 16 + g + 8) * HDIM + kc * 8);
        qf[kc][0] = r0[t];
        qf[kc][1] = r1[t];
        qf[kc][2] = r0[t + 4];
        qf[kc][3] = r1[t + 4];
    }

    float oacc[8][4];
#pragma unroll
    for (int nt = 0; nt < 8; ++nt)
#pragma unroll
        for (int j = 0; j < 4; ++j) oacc[nt][j] = 0.f;
    float m0 = -1e30f, m1 = -1e30f;
    float l0 = 0.f, l1 = 0.f;

    const unsigned long long* mb_row0 = g_Mb + ((size_t)b * NQ + q0 + w * 16 + g) * (NK / 64);
    const unsigned long long* mb_row1 = mb_row0 + 8 * (NK / 64);
    float* sPw = sP + (w * 16) * LDP;
    const int tsh = t * 16;

#pragma unroll
    for (int i = 0; i < 4; ++i) {
        int r = sr + i * 16;
        CP_ASYNC16(sKu + (r * LDK + sc4) * 4, Kg + (size_t)r * HDIM + sc4);
        CP_ASYNC16(sVu + (r * LDV + sc4) * 4, Vg + (size_t)r * HDIM + sc4);
    }
    CP_COMMIT();

    for (int kt = 0; kt < NK / 64; ++kt) {
        const int cur = kt & 1;
        __syncthreads();

        if (kt < NK / 64 - 1) {
            const int nxt = cur ^ 1;
            const float* Kn = Kg + (size_t)(kt + 1) * 64 * HDIM;
            const float* Vn = Vg + (size_t)(kt + 1) * 64 * HDIM;
#pragma unroll
            for (int i = 0; i < 4; ++i) {
                int r = sr + i * 16;
                CP_ASYNC16(sKu + (nxt * SKT + r * LDK + sc4) * 4, Kn + (size_t)r * HDIM + sc4);
                CP_ASYNC16(sVu + (nxt * SVT + r * LDV + sc4) * 4, Vn + (size_t)r * HDIM + sc4);
            }
            CP_COMMIT();
            asm volatile("cp.async.wait_group 1;" ::: "memory");
        } else {
            asm volatile("cp.async.wait_group 0;" ::: "memory");
        }
        __syncthreads();

        const float* sKc = sK + cur * SKT;
        const float* sVc = sV + cur * SVT;

        float sacc[8][4];
#pragma unroll
        for (int nt = 0; nt < 8; ++nt) {
#pragma unroll
            for (int j = 0; j < 4; ++j) sacc[nt][j] = 0.f;
#pragma unroll
            for (int kc = 0; kc < 8; ++kc) {
                uint32_t bfr[2];
                const float* kb = sKc + (nt * 8 + g) * LDK + kc * 8;
                bfr[0] = __float_as_uint(kb[t]);
                bfr[1] = __float_as_uint(kb[t + 4]);
                mma_tf32(sacc[nt], qf[kc], bfr);
            }
        }

        uint32_t ch0 = (uint32_t)(mb_row0[kt] >> tsh) & 0xffffu;
        uint32_t ch1 = (uint32_t)(mb_row1[kt] >> tsh) & 0xffffu;
        float tmax0 = -1e30f, tmax1 = -1e30f;
#pragma unroll
        for (int nt = 0; nt < 8; ++nt) {
            if (ch0 & (1u << (2 * nt)))     sacc[nt][0] = -1e30f;
            if (ch0 & (2u << (2 * nt)))     sacc[nt][1] = -1e30f;
            if (ch1 & (1u << (2 * nt)))     sacc[nt][2] = -1e30f;
            if (ch1 & (2u << (2 * nt)))     sacc[nt][3] = -1e30f;
            tmax0 = fmaxf(tmax0, fmaxf(sacc[nt][0], sacc[nt][1]));
            tmax1 = fmaxf(tmax1, fmaxf(sacc[nt][2], sacc[nt][3]));
        }
        tmax0 = fmaxf(tmax0, __shfl_xor_sync(0xffffffffu, tmax0, 1));
        tmax0 = fmaxf(tmax0, __shfl_xor_sync(0xffffffffu, tmax0, 2));
        tmax1 = fmaxf(tmax1, __shfl_xor_sync(0xffffffffu, tmax1, 1));
        tmax1 = fmaxf(tmax1, __shfl_xor_sync(0xffffffffu, tmax1, 2));

        float mn0 = fmaxf(m0, tmax0);
        float mn1 = fmaxf(m1, tmax1);
        float sc0 = ex2_approx(m0 - mn0);
        float sc1 = ex2_approx(m1 - mn1);
        m0 = mn0; m1 = mn1;

        float ps0 = 0.f, ps1 = 0.f;
#pragma unroll
        for (int nt = 0; nt < 8; ++nt) {
            float p0 = ex2_approx(sacc[nt][0] - mn0);
            float p1 = ex2_approx(sacc[nt][1] - mn0);
            float p2 = ex2_approx(sacc[nt][2] - mn1);
            float p3 = ex2_approx(sacc[nt][3] - mn1);
            ps0 += p0 + p1;
            ps1 += p2 + p3;
            float2 lo = make_float2(f2tf32_rna(p0), f2tf32_rna(p1));
            float2 hi = make_float2(f2tf32_rna(p2), f2tf32_rna(p3));
            *(float2*)(sPw + g * LDP + nt * 8 + 2 * t) = lo;
            *(float2*)(sPw + (g + 8) * LDP + nt * 8 + 2 * t) = hi;
        }
        ps0 += __shfl_xor_sync(0xffffffffu, ps0, 1);
        ps0 += __shfl_xor_sync(0xffffffffu, ps0, 2);
        ps1 += __shfl_xor_sync(0xffffffffu, ps1, 1);
        ps1 += __shfl_xor_sync(0xffffffffu, ps1, 2);
        l0 = l0 * sc0 + ps0;
        l1 = l1 * sc1 + ps1;

#pragma unroll
        for (int nt = 0; nt < 8; ++nt) {
            oacc[nt][0] *= sc0; oacc[nt][1] *= sc0;
            oacc[nt][2] *= sc1; oacc[nt][3] *= sc1;
        }
        __syncwarp();

#pragma unroll
        for (int kc = 0; kc < 8; ++kc) {
            uint32_t pa[4];
            const float* p0r = sPw + g * LDP + kc * 8;
            const float* p1r = sPw + (g + 8) * LDP + kc * 8;
            pa[0] = __float_as_uint(p0r[t]);
            pa[1] = __float_as_uint(p1r[t]);
            pa[2] = __float_as_uint(p0r[t + 4]);
            pa[3] = __float_as_uint(p1r[t + 4]);
#pragma unroll
            for (int nt = 0; nt < 8; ++nt) {
                uint32_t bfr[2];
                bfr[0] = __float_as_uint(sVc[(kc * 8 + t) * LDV + nt * 8 + g]);
                bfr[1] = __float_as_uint(sVc[(kc * 8 + t + 4) * LDV + nt * 8 + g]);
                mma_tf32(oacc[nt], pa, bfr);
            }
        }
        __syncwarp();
    }

    float inv0 = (l0 > 0.f) ? (1.f / l0) : 0.f;
    float inv1 = (l1 > 0.f) ? (1.f / l1) : 0.f;
    float* o0 = g_H + ((size_t)(b * NQ + q0 + w * 16 + g)) * DIN + h * HDIM;
    float* o1 = g_H + ((size_t)(b * NQ + q0 + w * 16 + g + 8)) * DIN + h * HDIM;
#pragma unroll
    for (int nt = 0; nt < 8; ++nt) {
        *(float2*)(o0 + nt * 8 + 2 * t) =
            make_float2(f2tf32_rna(oacc[nt][0] * inv0), f2tf32_rna(oacc[nt][1] * inv0));
        *(float2*)(o1 + nt * 8 + 2 * t) =
            make_float2(f2tf32_rna(oacc[nt][2] * inv1), f2tf32_rna(oacc[nt][3] * inv1));
    }
}

// ============================================================
extern "C" void kernel_launch(void* const* d_in, const int* in_sizes, int n_in,
                              void* d_out, int out_size)
{
    const float* q  = (const float*)d_in[0];
    const float* k  = (const float*)d_in[1];
    const float* v  = (const float*)d_in[2];
    const int*   mask = (const int*)d_in[3];
    const float* Wq = (const float*)d_in[4];
    const float* Wk = (const float*)d_in[5];
    const float* Wv = (const float*)d_in[6];
    const float* Wo = (const float*)d_in[7];
    float* out = (float*)d_out;

    float *pH;
    cudaGetSymbolAddress((void**)&pH, g_H);

    static bool attr_set = false;
    if (!attr_set) {
        cudaFuncSetAttribute(attn_mma,
                             cudaFuncAttributeMaxDynamicSharedMemorySize,
                             ATTN_SMEM);
        attr_set = true;
    }

    // Split + transpose QKV weights to bf16 hi/lo planes
    w_prep<<<(3 * 512 * 512) / 256, 256>>>(Wq, Wk, Wv);

    // QKV projections: bf16x3 tensor-core GEMM, outputs pre-rounded tf32
    qkv_bf<<<dim3(BN_TOT / 128, DIN / 128, 3), 256>>>(q, k, v);

    // Pack mask to permuted bitmasks (coalesced + REDUX)
    pack_mask<<<(BN_TOT * (NK / 64)) / 8, 256>>>(mask);

    // Flash attention (raw mma.sync tf32, cp.async double-buffered K/V)
    attn_mma<<<dim3(NQ / 128, BATCH, NHEADS), 256, ATTN_SMEM>>>();

    // Output projection: raw mma.sync tf32
    out_proj3<<<dim3(BN_TOT / 128, DIN / 128), 256>>>(pH, Wo, out);
}

// round 17
// speedup vs baseline: 1.8214x; 1.2001x over previous
#include <cuda_runtime.h>
#include <cuda_bf16.h>
#include <cuda_fp16.h>
#include <cstdint>

// Problem constants
#define BATCH   16
#define NQ      1024
#define NK      1024
#define DIN     512
#define NHEADS  8
#define HDIM    64
#define BN_TOT  (BATCH * NQ)       // 16384
#define NORM_F  0.125f             // 1/sqrt(64)
#define LOG2E   1.4426950408889634f

// -------- scratch (device globals: allocation-free) --------
__device__ __half g_Qh[(size_t)NHEADS * BN_TOT * HDIM];  // [h][bn][64], pre-scaled NORM*LOG2E
__device__ __half g_Kh[(size_t)NHEADS * BN_TOT * HDIM];  // [h][bn][64]
__device__ float  g_V [(size_t)NHEADS * BN_TOT * HDIM];  // [h][bn][64] fp32 (v_t input)
__device__ __half g_Vt[(size_t)NHEADS * BATCH * HDIM * NQ]; // [h][b][dim][key]
__device__ float  g_H [(size_t)BN_TOT * DIN];            // [bn][h*64+v], tf32-rounded
__device__ unsigned long long g_Mb[(size_t)BN_TOT * (NK / 64)];  // permuted mask bits
// bf16 hi/lo split of QKV weights, layout [op][n_global(512)][k(512)]
__device__ __nv_bfloat16 g_Wbh[(size_t)3 * 512 * 512];
__device__ __nv_bfloat16 g_Wbl[(size_t)3 * 512 * 512];

__device__ __forceinline__ float f2tf32_rna(float x) {
    uint32_t r;
    asm("cvt.rna.tf32.f32 %0, %1;" : "=r"(r) : "f"(x));
    return __uint_as_float(r);
}

__device__ __forceinline__ float ex2_approx(float x) {
    float r;
    asm("ex2.approx.f32 %0, %1;" : "=f"(r) : "f"(x));
    return r;
}

__device__ __forceinline__ uint32_t h2_pack(float lo, float hi) {
    __half2 h = __floats2half2_rn(lo, hi);   // .x = lo half (low 16 bits)
    return *(uint32_t*)&h;
}

__device__ __forceinline__ uint32_t smem_u32(const void* p) {
    uint32_t a;
    asm("{ .reg .u64 t; cvta.to.shared.u64 t, %1; cvt.u32.u64 %0, t; }"
        : "=r"(a) : "l"(p));
    return a;
}

#define CP_ASYNC16(dst_u32, src_ptr) \
    asm volatile("cp.async.cg.shared.global [%0], [%1], 16;" \
                 :: "r"(dst_u32), "l"(src_ptr) : "memory")
#define CP_COMMIT() asm volatile("cp.async.commit_group;" ::: "memory")

// m16n8k8 tf32 mma (g=lane>>2, t=lane&3): C c0(g,2t) c1(g,2t+1) c2(g+8,2t) c3(g+8,2t+1)
__device__ __forceinline__ void mma_tf32(float* c, const uint32_t* a, const uint32_t* b) {
    asm volatile(
        "mma.sync.aligned.m16n8k8.row.col.f32.tf32.tf32.f32 "
        "{%0,%1,%2,%3}, {%4,%5,%6,%7}, {%8,%9}, {%0,%1,%2,%3};"
        : "+f"(c[0]), "+f"(c[1]), "+f"(c[2]), "+f"(c[3])
        : "r"(a[0]), "r"(a[1]), "r"(a[2]), "r"(a[3]), "r"(b[0]), "r"(b[1]));
}

// m16n8k16 bf16 mma (2 bf16 per reg along K).
__device__ __forceinline__ void mma_bf16(float* c, const uint32_t* a,
                                         uint32_t b0, uint32_t b1) {
    asm volatile(
        "mma.sync.aligned.m16n8k16.row.col.f32.bf16.bf16.f32 "
        "{%0,%1,%2,%3}, {%4,%5,%6,%7}, {%8,%9}, {%0,%1,%2,%3};"
        : "+f"(c[0]), "+f"(c[1]), "+f"(c[2]), "+f"(c[3])
        : "r"(a[0]), "r"(a[1]), "r"(a[2]), "r"(a[3]), "r"(b0), "r"(b1));
}

// m16n8k16 fp16 mma, fp32 accumulate. Layout (g=lane>>2, t=lane&3):
//   A: a0(g, k=2t,2t+1) a1(g+8, same) a2(g, k=2t+8,2t+9) a3(g+8, same)
//   B: b0(k=2t,2t+1, n=g) b1(k=2t+8,2t+9, n=g)
//   C: c0(g,2t) c1(g,2t+1) c2(g+8,2t) c3(g+8,2t+1)
__device__ __forceinline__ void mma_f16(float* c, const uint32_t* a,
                                        uint32_t b0, uint32_t b1) {
    asm volatile(
        "mma.sync.aligned.m16n8k16.row.col.f32.f16.f16.f32 "
        "{%0,%1,%2,%3}, {%4,%5,%6,%7}, {%8,%9}, {%0,%1,%2,%3};"
        : "+f"(c[0]), "+f"(c[1]), "+f"(c[2]), "+f"(c[3])
        : "r"(a[0]), "r"(a[1]), "r"(a[2]), "r"(a[3]), "r"(b0), "r"(b1));
}

// ============================================================
// W prep: split QKV weights to bf16 hi/lo, transposed to [op][n][k].
// ============================================================
__global__ __launch_bounds__(256)
void w_prep(const float* __restrict__ Wq,
            const float* __restrict__ Wk,
            const float* __restrict__ Wv)
{
    size_t idx = (size_t)blockIdx.x * 256 + threadIdx.x;
    int k  = idx & 511;
    int n  = (idx >> 9) & 511;
    int op = (int)(idx >> 18);
    const float* W = (op == 0 ? Wq : (op == 1 ? Wk : Wv));
    float w = W[(size_t)((n >> 6) * 512 + k) * 64 + (n & 63)];
    __nv_bfloat16 hi = __float2bfloat16_rn(w);
    __nv_bfloat16 lo = __float2bfloat16_rn(w - __bfloat162float(hi));
    g_Wbh[idx] = hi;
    g_Wbl[idx] = lo;
}

// ============================================================
// QKV projection via bf16x3 split tensor-core GEMM (R13 core, measured best).
// R17 epilogue: Q (scaled) and K emitted as HALF; V stays fp32 (v_t converts).
// grid = (128 m-tiles, 4 n-tiles, 3 ops)
// ============================================================
#define QLD 40

__global__ __launch_bounds__(256, 2)
void qkv_bf(const float* __restrict__ q,
            const float* __restrict__ k,
            const float* __restrict__ v)
{
    __shared__ __nv_bfloat16 sAh[128 * QLD];
    __shared__ __nv_bfloat16 sAl[128 * QLD];
    __shared__ __nv_bfloat16 sWh[128 * QLD];
    __shared__ __nv_bfloat16 sWl[128 * QLD];

    const int tid  = threadIdx.x;
    const int w    = tid >> 5;
    const int lane = tid & 31;
    const int g    = lane >> 2;
    const int t    = lane & 3;
    const int wm   = w & 3;
    const int wn   = w >> 2;
    const int op   = blockIdx.z;
    const int m0   = blockIdx.x * 128;
    const int n0   = blockIdx.y * 128;

    const float* X = (op == 0 ? q : (op == 1 ? k : v));
    const __nv_bfloat16* Wh = g_Wbh + ((size_t)op * 512 + n0) * 512;
    const __nv_bfloat16* Wl = g_Wbl + ((size_t)op * 512 + n0) * 512;

    float acc[2][8][4];
#pragma unroll
    for (int mi = 0; mi < 2; ++mi)
#pragma unroll
        for (int nf = 0; nf < 8; ++nf)
#pragma unroll
            for (int j = 0; j < 4; ++j) acc[mi][nf][j] = 0.f;

    for (int c = 0; c < DIN / 32; ++c) {
        const int k0 = c * 32;
        if (c > 0) __syncthreads();

#pragma unroll
        for (int i = 0; i < 4; ++i) {
            int idx = tid + i * 256;
            int m  = idx >> 3;
            int kg = idx & 7;
            float4 xv = *(const float4*)(X + (size_t)(m0 + m) * DIN + k0 + kg * 4);
            union { __nv_bfloat16 b[4]; uint2 u; } uh, ul;
            float vv[4] = {xv.x, xv.y, xv.z, xv.w};
#pragma unroll
            for (int j = 0; j < 4; ++j) {
                __nv_bfloat16 hb = __float2bfloat16_rn(vv[j]);
                uh.b[j] = hb;
                ul.b[j] = __float2bfloat16_rn(vv[j] - __bfloat162float(hb));
            }
            *(uint2*)(sAh + m * QLD + kg * 4) = uh.u;
            *(uint2*)(sAl + m * QLD + kg * 4) = ul.u;
        }
#pragma unroll
        for (int i = 0; i < 2; ++i) {
            int s  = tid + i * 256;
            int n  = s >> 2;
            int kg = s & 3;
            *(uint4*)(sWh + n * QLD + kg * 8) =
                *(const uint4*)(Wh + (size_t)n * 512 + k0 + kg * 8);
            *(uint4*)(sWl + n * QLD + kg * 8) =
                *(const uint4*)(Wl + (size_t)n * 512 + k0 + kg * 8);
        }
        __syncthreads();

#pragma unroll
        for (int kc2 = 0; kc2 < 2; ++kc2) {
            const int kb = kc2 * 16;
            uint32_t ah[2][4], al[2][4];
#pragma unroll
            for (int mi = 0; mi < 2; ++mi) {
                int r0 = wm * 32 + mi * 16 + g;
                int r1 = r0 + 8;
                ah[mi][0] = *(const uint32_t*)(sAh + r0 * QLD + kb + 2 * t);
                ah[mi][1] = *(const uint32_t*)(sAh + r1 * QLD + kb + 2 * t);
                ah[mi][2] = *(const uint32_t*)(sAh + r0 * QLD + kb + 8 + 2 * t);
                ah[mi][3] = *(const uint32_t*)(sAh + r1 * QLD + kb + 8 + 2 * t);
                al[mi][0] = *(const uint32_t*)(sAl + r0 * QLD + kb + 2 * t);
                al[mi][1] = *(const uint32_t*)(sAl + r1 * QLD + kb + 2 * t);
                al[mi][2] = *(const uint32_t*)(sAl + r0 * QLD + kb + 8 + 2 * t);
                al[mi][3] = *(const uint32_t*)(sAl + r1 * QLD + kb + 8 + 2 * t);
            }
#pragma unroll
            for (int nf = 0; nf < 8; ++nf) {
                int col = wn * 64 + nf * 8 + g;
                uint32_t bh0 = *(const uint32_t*)(sWh + col * QLD + kb + 2 * t);
                uint32_t bh1 = *(const uint32_t*)(sWh + col * QLD + kb + 8 + 2 * t);
                uint32_t bl0 = *(const uint32_t*)(sWl + col * QLD + kb + 2 * t);
                uint32_t bl1 = *(const uint32_t*)(sWl + col * QLD + kb + 8 + 2 * t);
                mma_bf16(acc[0][nf], ah[0], bh0, bh1);   // hi*hi
                mma_bf16(acc[1][nf], ah[1], bh0, bh1);
                mma_bf16(acc[0][nf], ah[0], bl0, bl1);   // hi*lo
                mma_bf16(acc[1][nf], ah[1], bl0, bl1);
                mma_bf16(acc[0][nf], al[0], bh0, bh1);   // lo*hi
                mma_bf16(acc[1][nf], al[1], bh0, bh1);
            }
        }
    }

    const int hb = (n0 >> 6) + wn;
    if (op == 2) {
        // V: fp32, per-head layout (v_t converts+transposes)
#pragma unroll
        for (int mi = 0; mi < 2; ++mi) {
            int r0 = m0 + wm * 32 + mi * 16 + g;
            float* o0 = g_V + ((size_t)hb * BN_TOT + r0) * HDIM;
            float* o1 = g_V + ((size_t)hb * BN_TOT + r0 + 8) * HDIM;
#pragma unroll
            for (int nf = 0; nf < 8; ++nf) {
                *(float2*)(o0 + nf * 8 + 2 * t) = make_float2(acc[mi][nf][0], acc[mi][nf][1]);
                *(float2*)(o1 + nf * 8 + 2 * t) = make_float2(acc[mi][nf][2], acc[mi][nf][3]);
            }
        }
    } else {
        const float osc = (op == 0) ? (NORM_F * LOG2E) : 1.0f;
        __half* Ch = (op == 0) ? g_Qh : g_Kh;
#pragma unroll
        for (int mi = 0; mi < 2; ++mi) {
            int r0 = m0 + wm * 32 + mi * 16 + g;
            __half* o0 = Ch + ((size_t)hb * BN_TOT + r0) * HDIM;
            __half* o1 = Ch + ((size_t)hb * BN_TOT + r0 + 8) * HDIM;
#pragma unroll
            for (int nf = 0; nf < 8; ++nf) {
                *(uint32_t*)(o0 + nf * 8 + 2 * t) = h2_pack(acc[mi][nf][0] * osc, acc[mi][nf][1] * osc);
                *(uint32_t*)(o1 + nf * 8 + 2 * t) = h2_pack(acc[mi][nf][2] * osc, acc[mi][nf][3] * osc);
            }
        }
    }
}

// ============================================================
// V transpose+convert: g_V [h][bn][64] fp32 -> g_Vt [h][b][dim][key] half.
// Block: one 128-key x 64-dim tile; smem round-trip; coalesced both sides.
// grid = (8 keyblks, 16 b, 8 h), 256 threads.
// ============================================================
#define VT_LD 136
__global__ __launch_bounds__(256)
void v_t()
{
    __shared__ __align__(16) __half sT[64 * VT_LD];

    const int tid = threadIdx.x;
    const int m0  = blockIdx.x * 128;
    const int b   = blockIdx.y;
    const int h   = blockIdx.z;

    const float* src = g_V + (((size_t)(h * BATCH + b)) * NQ + m0) * HDIM;
#pragma unroll
    for (int i = 0; i < 8; ++i) {
        int idx = tid + i * 256;
        int key = idx >> 4;
        int c4  = (idx & 15) * 4;
        float4 xv = *(const float4*)(src + (size_t)key * HDIM + c4);
        sT[(c4 + 0) * VT_LD + key] = __float2half_rn(xv.x);
        sT[(c4 + 1) * VT_LD + key] = __float2half_rn(xv.y);
        sT[(c4 + 2) * VT_LD + key] = __float2half_rn(xv.z);
        sT[(c4 + 3) * VT_LD + key] = __float2half_rn(xv.w);
    }
    __syncthreads();

    __half* dst = g_Vt + (((size_t)(h * BATCH + b)) * HDIM) * NQ + m0;
#pragma unroll
    for (int i = 0; i < 4; ++i) {
        int idx = tid + i * 256;
        int dim = idx >> 4;
        int kb8 = (idx & 15) * 8;
        *(uint4*)(dst + (size_t)dim * NQ + kb8) = *(const uint4*)(sT + dim * VT_LD + kb8);
    }
}

// ============================================================
// Mask pack, coalesced + REDUX (R16 — works, bit-identical permutation).
// ============================================================
__global__ __launch_bounds__(256)
void pack_mask(const int* __restrict__ mask)
{
    int w = (blockIdx.x * 256 + threadIdx.x) >> 5;
    int L = threadIdx.x & 31;
    int2 m2 = *(const int2*)(mask + (size_t)w * 64 + 2 * L);
    int pos0 = (L & 3) * 16 + (L >> 2) * 2;
    unsigned long long bits =
        ((unsigned long long)((m2.x != 0 ? 1u : 0u) | (m2.y != 0 ? 2u : 0u))) << pos0;
    unsigned lo = __reduce_or_sync(0xffffffffu, (unsigned)bits);
    unsigned hi = __reduce_or_sync(0xffffffffu, (unsigned)(bits >> 32));
    if (L == 0)
        g_Mb[w] = ((unsigned long long)hi << 32) | (unsigned long long)lo;
}

// ============================================================
// Out projection with RAW mma.sync tf32 (R13 — measured good). Unchanged.
// ============================================================
#define OP_LDH 40
#define OP_LDW 136

__global__ __launch_bounds__(256, 2)
void out_proj3(const float* __restrict__ A,
               const float* __restrict__ B,
               float* __restrict__ C)
{
    __shared__ float sH[128 * OP_LDH];
    __shared__ float sW[32 * OP_LDW];

    const int tid  = threadIdx.x;
    const int w    = tid >> 5;
    const int lane = tid & 31;
    const int g    = lane >> 2;
    const int t    = lane & 3;
    const int wm   = w & 3;
    const int wn   = w >> 2;
    const int m0   = blockIdx.x * 128;
    const int n0   = blockIdx.y * 128;

    const float* At = A + (size_t)m0 * DIN;
    const float* Bt = B + n0;
    const int c4b = tid & 31;

    float acc[2][8][4];
#pragma unroll
    for (int mi = 0; mi < 2; ++mi)
#pragma unroll
        for (int nf = 0; nf < 8; ++nf)
#pragma unroll
            for (int j = 0; j < 4; ++j) acc[mi][nf][j] = 0.f;

    float4 ar[4], br[4];
#pragma unroll
    for (int i = 0; i < 4; ++i) {
        int idx = tid + i * 256;
        ar[i] = *(const float4*)(At + (size_t)(idx >> 3) * DIN + (idx & 7) * 4);
        br[i] = *(const float4*)(Bt + (size_t)((tid >> 5) + i * 8) * DIN + c4b * 4);
    }
#pragma unroll
    for (int i = 0; i < 4; ++i) {
        int idx = tid + i * 256;
        *(float4*)(sH + (idx >> 3) * OP_LDH + (idx & 7) * 4) = ar[i];
        float4 bv = br[i];
        bv.x = f2tf32_rna(bv.x); bv.y = f2tf32_rna(bv.y);
        bv.z = f2tf32_rna(bv.z); bv.w = f2tf32_rna(bv.w);
        *(float4*)(sW + ((tid >> 5) + i * 8) * OP_LDW + c4b * 4) = bv;
    }
    __syncthreads();

    for (int c = 0; c < DIN / 32; ++c) {
        if (c < DIN / 32 - 1) {
            const int k0n = (c + 1) * 32;
#pragma unroll
            for (int i = 0; i < 4; ++i) {
                int idx = tid + i * 256;
                ar[i] = *(const float4*)(At + (size_t)(idx >> 3) * DIN + k0n + (idx & 7) * 4);
                br[i] = *(const float4*)(Bt + (size_t)(k0n + (tid >> 5) + i * 8) * DIN + c4b * 4);
            }
        }

#pragma unroll
        for (int kc = 0; kc < 4; ++kc) {
            uint32_t af[2][4];
#pragma unroll
            for (int mi = 0; mi < 2; ++mi) {
                const float* r0 = sH + (wm * 32 + mi * 16 + g) * OP_LDH + kc * 8;
                const float* r1 = sH + (wm * 32 + mi * 16 + g + 8) * OP_LDH + kc * 8;
                af[mi][0] = __float_as_uint(r0[t]);
                af[mi][1] = __float_as_uint(r1[t]);
                af[mi][2] = __float_as_uint(r0[t + 4]);
                af[mi][3] = __float_as_uint(r1[t + 4]);
            }
#pragma unroll
            for (int nf = 0; nf < 8; ++nf) {
                uint32_t bfr[2];
                bfr[0] = __float_as_uint(sW[(kc * 8 + t) * OP_LDW + wn * 64 + nf * 8 + g]);
                bfr[1] = __float_as_uint(sW[(kc * 8 + t + 4) * OP_LDW + wn * 64 + nf * 8 + g]);
                mma_tf32(acc[0][nf], af[0], bfr);
                mma_tf32(acc[1][nf], af[1], bfr);
            }
        }
        __syncthreads();

        if (c < DIN / 32 - 1) {
#pragma unroll
            for (int i = 0; i < 4; ++i) {
                int idx = tid + i * 256;
                *(float4*)(sH + (idx >> 3) * OP_LDH + (idx & 7) * 4) = ar[i];
                float4 bv = br[i];
                bv.x = f2tf32_rna(bv.x); bv.y = f2tf32_rna(bv.y);
                bv.z = f2tf32_rna(bv.z); bv.w = f2tf32_rna(bv.w);
                *(float4*)(sW + ((tid >> 5) + i * 8) * OP_LDW + c4b * 4) = bv;
            }
            __syncthreads();
        }
    }

#pragma unroll
    for (int mi = 0; mi < 2; ++mi) {
        float* r0 = C + (size_t)(m0 + wm * 32 + mi * 16 + g) * DIN + n0 + wn * 64;
        float* r1 = C + (size_t)(m0 + wm * 32 + mi * 16 + g + 8) * DIN + n0 + wn * 64;
#pragma unroll
        for (int nf = 0; nf < 8; ++nf) {
            *(float2*)(r0 + nf * 8 + 2 * t) = make_float2(acc[mi][nf][0], acc[mi][nf][1]);
            *(float2*)(r1 + nf * 8 + 2 * t) = make_float2(acc[mi][nf][2], acc[mi][nf][3]);
        }
    }
}

// ============================================================
// Flash attention, fp16 m16n8k16 (fp32 accum), HW EX2,
// cp.async double-buffered K/V^T. P stays in registers (A-frags = softmax
// output pairs). smem 36 KB. 2 CTAs/SM.
// ============================================================
#define LDKH 72            // halves per K row (64 + 8 pad); 144 B, 16B-aligned
#define LDVH 72            // halves per V^T row
#define SKTH (64 * LDKH)   // halves per K tile buffer
#define SVTH (64 * LDVH)
#define ATTN_SMEM ((2 * SKTH + 2 * SVTH) * 2)

__global__ __launch_bounds__(256, 2)
void attn_f16()
{
    extern __shared__ __half smh[];
    __half* sK = smh;                 // [2][64][LDKH]
    __half* sV = smh + 2 * SKTH;      // [2][64][LDVH]  (V^T: row=dim, col=key)

    const int tid  = threadIdx.x;
    const int w    = tid >> 5;
    const int lane = tid & 31;
    const int g    = lane >> 2;
    const int t    = lane & 3;
    const int q0   = blockIdx.x * 128;
    const int b    = blockIdx.y;
    const int h    = blockIdx.z;

    const __half* Qg = g_Qh + ((size_t)(h * BATCH + b) * NQ + q0) * HDIM;
    const __half* Kg = g_Kh + (size_t)(h * BATCH + b) * NK * HDIM;
    const __half* Vt = g_Vt + ((size_t)(h * BATCH + b) * HDIM) * NQ;

    // staging: idx = tid + i*256 -> row = idx>>3 (0..63), chunk8 = (idx&7)*8 halves
    const int srow = tid >> 3;
    const int sc8  = (tid & 7) * 8;
    const uint32_t sKu = smem_u32(sK);
    const uint32_t sVu = smem_u32(sV);

    // Q A-frags (fp16 m16n8k16): qf[kc] covers dims kc*16..+15
    uint32_t qf[4][4];
#pragma unroll
    for (int kc = 0; kc < 4; ++kc) {
        const uint32_t* r0 = (const uint32_t*)(Qg + (size_t)(w * 16 + g) * HDIM + kc * 16);
        const uint32_t* r1 = (const uint32_t*)(Qg + (size_t)(w * 16 + g + 8) * HDIM + kc * 16);
        qf[kc][0] = r0[t];
        qf[kc][1] = r1[t];
        qf[kc][2] = r0[t + 4];
        qf[kc][3] = r1[t + 4];
    }

    float oacc[8][4];
#pragma unroll
    for (int nf = 0; nf < 8; ++nf)
#pragma unroll
        for (int j = 0; j < 4; ++j) oacc[nf][j] = 0.f;
    float m0 = -1e30f, m1 = -1e30f;
    float l0 = 0.f, l1 = 0.f;

    const unsigned long long* mb_row0 = g_Mb + ((size_t)b * NQ + q0 + w * 16 + g) * (NK / 64);
    const unsigned long long* mb_row1 = mb_row0 + 8 * (NK / 64);
    const int tsh = t * 16;

    // ---- prologue: tile 0 into buffer 0 ----
#pragma unroll
    for (int i = 0; i < 2; ++i) {
        int r = srow + i * 32;
        CP_ASYNC16(sKu + (r * LDKH + sc8) * 2, Kg + (size_t)r * HDIM + sc8);
        CP_ASYNC16(sVu + (r * LDVH + sc8) * 2, Vt + (size_t)r * NQ + sc8);
    }
    CP_COMMIT();

    for (int kt = 0; kt < NK / 64; ++kt) {
        const int cur = kt & 1;
        __syncthreads();

        if (kt < NK / 64 - 1) {
            const int nxt = cur ^ 1;
            const __half* Kn = Kg + (size_t)(kt + 1) * 64 * HDIM;
            const __half* Vn = Vt + (size_t)(kt + 1) * 64;     // next 64 keys
#pragma unroll
            for (int i = 0; i < 2; ++i) {
                int r = srow + i * 32;
                CP_ASYNC16(sKu + (nxt * SKTH + r * LDKH + sc8) * 2, Kn + (size_t)r * HDIM + sc8);
                CP_ASYNC16(sVu + (nxt * SVTH + r * LDVH + sc8) * 2, Vn + (size_t)r * NQ + sc8);
            }
            CP_COMMIT();
            asm volatile("cp.async.wait_group 1;" ::: "memory");
        } else {
            asm volatile("cp.async.wait_group 0;" ::: "memory");
        }
        __syncthreads();

        const __half* sKc = sK + cur * SKTH;
        const __half* sVc = sV + cur * SVTH;

        // ---- S = Q K^T: per nt (8 keys), 4 fp16 MMAs over dims ----
        float sacc[8][4];
#pragma unroll
        for (int nt = 0; nt < 8; ++nt) {
#pragma unroll
            for (int j = 0; j < 4; ++j) sacc[nt][j] = 0.f;
            const uint32_t* kb = (const uint32_t*)(sKc + (nt * 8 + g) * LDKH);
#pragma unroll
            for (int kc = 0; kc < 4; ++kc)
                mma_f16(sacc[nt], qf[kc], kb[kc * 8 + t], kb[kc * 8 + 4 + t]);
        }

        // ---- masked online softmax (registers) ----
        uint32_t ch0 = (uint32_t)(mb_row0[kt] >> tsh) & 0xffffu;
        uint32_t ch1 = (uint32_t)(mb_row1[kt] >> tsh) & 0xffffu;
        float tmax0 = -1e30f, tmax1 = -1e30f;
#pragma unroll
        for (int nt = 0; nt < 8; ++nt) {
            if (ch0 & (1u << (2 * nt)))     sacc[nt][0] = -1e30f;
            if (ch0 & (2u << (2 * nt)))     sacc[nt][1] = -1e30f;
            if (ch1 & (1u << (2 * nt)))     sacc[nt][2] = -1e30f;
            if (ch1 & (2u << (2 * nt)))     sacc[nt][3] = -1e30f;
            tmax0 = fmaxf(tmax0, fmaxf(sacc[nt][0], sacc[nt][1]));
            tmax1 = fmaxf(tmax1, fmaxf(sacc[nt][2], sacc[nt][3]));
        }
        tmax0 = fmaxf(tmax0, __shfl_xor_sync(0xffffffffu, tmax0, 1));
        tmax0 = fmaxf(tmax0, __shfl_xor_sync(0xffffffffu, tmax0, 2));
        tmax1 = fmaxf(tmax1, __shfl_xor_sync(0xffffffffu, tmax1, 1));
        tmax1 = fmaxf(tmax1, __shfl_xor_sync(0xffffffffu, tmax1, 2));

        float mn0 = fmaxf(m0, tmax0);
        float mn1 = fmaxf(m1, tmax1);
        float sc0 = ex2_approx(m0 - mn0);
        float sc1 = ex2_approx(m1 - mn1);
        m0 = mn0; m1 = mn1;

        // P pairs packed as fp16 A-fragments (no smem!)
        uint32_t ph_lo[8], ph_hi[8];
        float ps0 = 0.f, ps1 = 0.f;
#pragma unroll
        for (int nt = 0; nt < 8; ++nt) {
            float p0 = ex2_approx(sacc[nt][0] - mn0);
            float p1 = ex2_approx(sacc[nt][1] - mn0);
            float p2 = ex2_approx(sacc[nt][2] - mn1);
            float p3 = ex2_approx(sacc[nt][3] - mn1);
            ps0 += p0 + p1;
            ps1 += p2 + p3;
            ph_lo[nt] = h2_pack(p0, p1);   // row g,   keys nt*8+2t, +1
            ph_hi[nt] = h2_pack(p2, p3);   // row g+8
        }
        ps0 += __shfl_xor_sync(0xffffffffu, ps0, 1);
        ps0 += __shfl_xor_sync(0xffffffffu, ps0, 2);
        ps1 += __shfl_xor_sync(0xffffffffu, ps1, 1);
        ps1 += __shfl_xor_sync(0xffffffffu, ps1, 2);
        l0 = l0 * sc0 + ps0;
        l1 = l1 * sc1 + ps1;

#pragma unroll
        for (int nf = 0; nf < 8; ++nf) {
            oacc[nf][0] *= sc0; oacc[nf][1] *= sc0;
            oacc[nf][2] *= sc1; oacc[nf][3] *= sc1;
        }

        // ---- O += P V: per key-block kc (4), A from regs, B from V^T smem ----
#pragma unroll
        for (int kc = 0; kc < 4; ++kc) {
            uint32_t pa[4] = {ph_lo[2 * kc], ph_hi[2 * kc],
                              ph_lo[2 * kc + 1], ph_hi[2 * kc + 1]};
#pragma unroll
            for (int nf = 0; nf < 8; ++nf) {
                const uint32_t* vb = (const uint32_t*)(sVc + (nf * 8 + g) * LDVH);
                mma_f16(oacc[nf], pa, vb[kc * 8 + t], vb[kc * 8 + 4 + t]);
            }
        }
    }

    // Normalize, pre-round to tf32, write g_H
    float inv0 = (l0 > 0.f) ? (1.f / l0) : 0.f;
    float inv1 = (l1 > 0.f) ? (1.f / l1) : 0.f;
    float* o0 = g_H + ((size_t)(b * NQ + q0 + w * 16 + g)) * DIN + h * HDIM;
    float* o1 = g_H + ((size_t)(b * NQ + q0 + w * 16 + g + 8)) * DIN + h * HDIM;
#pragma unroll
    for (int nf = 0; nf < 8; ++nf) {
        *(float2*)(o0 + nf * 8 + 2 * t) =
            make_float2(f2tf32_rna(oacc[nf][0] * inv0), f2tf32_rna(oacc[nf][1] * inv0));
        *(float2*)(o1 + nf * 8 + 2 * t) =
            make_float2(f2tf32_rna(oacc[nf][2] * inv1), f2tf32_rna(oacc[nf][3] * inv1));
    }
}

// ============================================================
extern "C" void kernel_launch(void* const* d_in, const int* in_sizes, int n_in,
                              void* d_out, int out_size)
{
    const float* q  = (const float*)d_in[0];
    const float* k  = (const float*)d_in[1];
    const float* v  = (const float*)d_in[2];
    const int*   mask = (const int*)d_in[3];
    const float* Wq = (const float*)d_in[4];
    const float* Wk = (const float*)d_in[5];
    const float* Wv = (const float*)d_in[6];
    const float* Wo = (const float*)d_in[7];
    float* out = (float*)d_out;

    float *pH;
    cudaGetSymbolAddress((void**)&pH, g_H);

    static bool attr_set = false;
    if (!attr_set) {
        cudaFuncSetAttribute(attn_f16,
                             cudaFuncAttributeMaxDynamicSharedMemorySize,
                             ATTN_SMEM);
        attr_set = true;
    }

    // Split + transpose QKV weights to bf16 hi/lo planes
    w_prep<<<(3 * 512 * 512) / 256, 256>>>(Wq, Wk, Wv);

    // QKV projections: bf16x3 tensor-core GEMM; Q/K emitted half, V fp32
    qkv_bf<<<dim3(BN_TOT / 128, DIN / 128, 3), 256>>>(q, k, v);

    // V transpose + half convert
    v_t<<<dim3(NQ / 128, BATCH, NHEADS), 256>>>();

    // Pack mask to permuted bitmasks
    pack_mask<<<(BN_TOT * (NK / 64)) / 8, 256>>>(mask);

    // Flash attention (fp16 mma, register P, cp.async double-buffered)
    attn_f16<<<dim3(NQ / 128, BATCH, NHEADS), 256, ATTN_SMEM>>>();

    // Output projection: raw mma.sync tf32
    out_proj3<<<dim3(BN_TOT / 128, DIN / 128), 256>>>(pH, Wo, out);
}